// round 12
// baseline (speedup 1.0000x reference)
#include <cuda_runtime.h>
#include <cstdint>
#include <math.h>

#define LEVELS 3
#define BINS 9
#define NATOMS 51
#define ADIM 6
#define NB 4096
#define SLAB 8262                 // full per-batch floats (162*51)
#define NSIX 6
#define TROWS 27                  // rows per sixth
#define TSLAB 1377                // floats per sixth (27*51)
#define TSLAB_BYTES 5508          // == 4 mod 16
#define LOAD_BYTES 5520           // fixed 16B-multiple bulk-load size
#define V_MIN_C (-10.0f)
#define V_MAX_C (10.0f)
#define DZ_C (0.4f)

#define THREADS 64
#define GRID (NB * NSIX)          // 24576

// dyn smem (16B-aligned base):
//   [0,16)            mbarrier
//   [16, 16+5520)     input slot (data at +m)
#define OFF_MBAR 0
#define OFF_IN   16
#define DYN_BYTES (OFF_IN + LOAD_BYTES)    // 5536

__global__ __launch_bounds__(THREADS)
void c2f_kernel(const float* __restrict__ q,
                const float* __restrict__ reward,
                const float* __restrict__ discount,
                const float* __restrict__ act,
                const float* __restrict__ support,
                const float* __restrict__ low0,
                const float* __restrict__ high0,
                float* __restrict__ out)
{
    const int T = blockIdx.x;             // sixth index
    const int t = threadIdx.x;
    const int b = T / NSIX;               // batch element
    const int sixth = T - b * NSIX;
    const int m = (T & 3) * 4;            // byte misalignment of T*5508 mod 16

    extern __shared__ __align__(16) char dyn[];
    const uint32_t smem_base = (uint32_t)__cvta_generic_to_shared(dyn);
    const uint32_t mbar = smem_base + OFF_MBAR;

    float* sp = reinterpret_cast<float*>(dyn + OFF_IN + m);   // staged probs

    __shared__ __align__(16) float4 stbl[NATOMS];   // (wl, wu, lower_bits, 0)

    // ---- t0: init mbar, fire TMA immediately (tables overlap the flight) ----
    if (t == 0) {
        asm volatile("mbarrier.init.shared.b64 [%0], 1;" :: "r"(mbar) : "memory");
        const char* src = reinterpret_cast<const char*>(q) + (size_t)T * TSLAB_BYTES - m;
        asm volatile("mbarrier.arrive.expect_tx.shared.b64 _, [%0], %1;"
                     :: "r"(mbar), "r"((uint32_t)LOAD_BYTES) : "memory");
        asm volatile("cp.async.bulk.shared::cta.global.mbarrier::complete_tx::bytes "
                     "[%0], [%1], %2, [%3];"
                     :: "r"(smem_base + OFF_IN), "l"(src),
                        "r"((uint32_t)LOAD_BYTES), "r"(mbar) : "memory");
    }

    // ---- projection table (block-uniform; depends only on b) ----
    if (t < NATOMS) {
        const float r = reward[b];
        const float d = discount[b];
        const float z = support[t];
        float Tz = fminf(fmaxf(r + d * z, V_MIN_C), V_MAX_C);
        float bc = (Tz - V_MIN_C) / DZ_C;
        int lo = (int)floorf(bc);
        int up = (int)ceilf(bc);
        if (up > 0 && lo == up) lo -= 1;              // reference fixup 1
        if (lo < NATOMS - 1 && lo == up) up += 1;     // reference fixup 2 => up==lo+1
        stbl[t] = make_float4((float)up - bc, bc - (float)lo,
                              __int_as_float(lo), 0.0f);
    }

    // ---- encode + decode: only in the sixth==0 CTA of each batch element ----
    if (sixth == 0 && t >= 52 && t < 52 + ADIM) {
        const int dim = t - 52;
        const float a = act[b * ADIM + dim];
        float low = low0[dim], high = high0[dim];
        float idx[LEVELS];
        #pragma unroll
        for (int lvl = 0; lvl < LEVELS; lvl++) {
            float sr = (high - low) / (float)BINS;
            float id = floorf((a - low) / sr);
            id = fminf(fmaxf(id, 0.0f), (float)(BINS - 1));
            float na = fminf(fmaxf(low + sr * id, -1.0f), 1.0f);
            low  = fmaxf(-1.0f, na);
            high = fminf(1.0f, na + sr);
            idx[lvl] = id;
        }
        low = low0[dim]; high = high0[dim];
        #pragma unroll
        for (int lvl = 0; lvl < LEVELS; lvl++) {
            float sr = (high - low) / (float)BINS;
            float cont = low + sr * idx[lvl];
            low  = fmaxf(-1.0f, cont);
            high = fminf(1.0f, cont + sr);
        }
        out[(size_t)NB * SLAB + (size_t)b * ADIM + dim] = 0.5f * (high + low);
    }

    __syncthreads();   // mbar init + table visible to all

    // ---- wait for the slab ----
    asm volatile(
        "{\n\t"
        ".reg .pred P;\n\t"
        "WAIT_%=:\n\t"
        "mbarrier.try_wait.parity.acquire.cta.shared::cta.b64 P, [%0], 0, 0x989680;\n\t"
        "@!P bra WAIT_%=;\n\t"
        "}"
        :: "r"(mbar) : "memory");

    // ---- walk: one thread per row, single pass j=0..50, writing DIRECTLY to
    //      global memory. Each output element is written exactly once; the
    //      per-thread row (204 B contiguous) merges into full sectors in L2.
    if (t < TROWS) {
        const float* pr = sp + t * NATOMS;               // stride 51 -> conflict-free
        float* po = out + (size_t)T * TSLAB + t * NATOMS; // global row
        int kcur = __float_as_int(stbl[0].z);
        for (int k = 0; k < kcur; k++) po[k] = 0.0f;     // prefix zeros
        float accA = 0.0f, accB = 0.0f, carryB = 0.0f;
        #pragma unroll 1
        for (int j = 0; j < NATOMS; j++) {
            const float4 tb = stbl[j];       // LDS.128 broadcast
            const int kj = __float_as_int(tb.z);
            if (kj != kcur) {                // uniform branch
                po[kcur] = accA + carryB;
                if (kj == kcur + 1) {
                    carryB = accB;
                } else {
                    po[kcur + 1] = accB;
                    for (int k = kcur + 2; k < kj; k++) po[k] = 0.0f;  // gap zeros
                    carryB = 0.0f;
                }
                accA = 0.0f; accB = 0.0f; kcur = kj;
            }
            const float p = pr[j];
            accA = fmaf(p, tb.x, accA);
            accB = fmaf(p, tb.y, accB);
        }
        po[kcur] = accA + carryB;
        po[kcur + 1] = accB;                 // kcur <= 49 -> safe
        for (int k = kcur + 2; k < NATOMS; k++) po[k] = 0.0f;  // suffix zeros
    }
}

extern "C" void kernel_launch(void* const* d_in, const int* in_sizes, int n_in,
                              void* d_out, int out_size)
{
    const float* q        = (const float*)d_in[0];
    const float* reward   = (const float*)d_in[1];
    const float* discount = (const float*)d_in[2];
    const float* act      = (const float*)d_in[3];
    const float* support  = (const float*)d_in[4];
    const float* low0     = (const float*)d_in[5];
    const float* high0    = (const float*)d_in[6];
    float* out = (float*)d_out;

    cudaFuncSetAttribute(c2f_kernel, cudaFuncAttributeMaxDynamicSharedMemorySize,
                         DYN_BYTES);
    c2f_kernel<<<GRID, THREADS, DYN_BYTES>>>(q, reward, discount, act, support,
                                             low0, high0, out);
}

// round 13
// speedup vs baseline: 3.2162x; 3.2162x over previous
#include <cuda_runtime.h>
#include <cstdint>
#include <math.h>

#define LEVELS 3
#define BINS 9
#define NATOMS 51
#define ADIM 6
#define NB 4096
#define SLAB 8262                 // full per-batch floats (162*51)
#define NSIX 6
#define TROWS 27                  // rows per sixth
#define TSLAB 1377                // floats per sixth (27*51)
#define TSLAB_BYTES 5508          // == 4 mod 16
#define LOAD_BYTES 5520           // fixed 16B-multiple bulk-load size
#define V_MIN_C (-10.0f)
#define V_MAX_C (10.0f)
#define DZ_C (0.4f)

#define THREADS 128
#define GRID (NB * NSIX / 2)      // 12288 CTAs, 2 units each

// dyn smem (16B-aligned base):
//   [0,16)    mbar0 @0, mbar1 @8
//   [16,      +5520)  in0   (data at +m0)
//   [5536,    +5520)  in1   (data at +m1)
//   [11056,   +5520)  out0  (data at +m0)
//   [16576,   +5520)  out1  (data at +m1)
#define OFF_MBAR 0
#define OFF_IN0  16
#define OFF_IN1  (OFF_IN0 + LOAD_BYTES)     // 5536
#define OFF_OUT0 (OFF_IN1 + LOAD_BYTES)     // 11056
#define OFF_OUT1 (OFF_OUT0 + LOAD_BYTES)    // 16576
#define DYN_BYTES (OFF_OUT1 + LOAD_BYTES)   // 22096

__global__ __launch_bounds__(THREADS)
void c2f_kernel(const float* __restrict__ q,
                const float* __restrict__ reward,
                const float* __restrict__ discount,
                const float* __restrict__ act,
                const float* __restrict__ support,
                const float* __restrict__ low0,
                const float* __restrict__ high0,
                float* __restrict__ out)
{
    const int c = blockIdx.x;
    const int t = threadIdx.x;
    const int U0 = 2 * c;                 // first sixth
    const int U1 = 2 * c + 1;             // second sixth (same batch element)
    const int b  = c / 3;                 // batch element (2c/6)
    const int m0 = (U0 & 3) * 4;          // byte misalignment of U*5508 mod 16
    const int m1 = (U1 & 3) * 4;

    extern __shared__ __align__(16) char dyn[];
    const uint32_t smem_base = (uint32_t)__cvta_generic_to_shared(dyn);

    __shared__ __align__(16) float4 stbl[NATOMS];   // (wl, wu, lower_bits, 0)

    // ---- t0: init both mbars, fire both TMA loads immediately ----
    if (t == 0) {
        asm volatile("mbarrier.init.shared.b64 [%0], 1;" :: "r"(smem_base + OFF_MBAR) : "memory");
        asm volatile("mbarrier.init.shared.b64 [%0], 1;" :: "r"(smem_base + OFF_MBAR + 8) : "memory");
        const char* s0 = reinterpret_cast<const char*>(q) + (size_t)U0 * TSLAB_BYTES - m0;
        const char* s1 = reinterpret_cast<const char*>(q) + (size_t)U1 * TSLAB_BYTES - m1;
        asm volatile("mbarrier.arrive.expect_tx.shared.b64 _, [%0], %1;"
                     :: "r"(smem_base + OFF_MBAR), "r"((uint32_t)LOAD_BYTES) : "memory");
        asm volatile("cp.async.bulk.shared::cta.global.mbarrier::complete_tx::bytes "
                     "[%0], [%1], %2, [%3];"
                     :: "r"(smem_base + OFF_IN0), "l"(s0),
                        "r"((uint32_t)LOAD_BYTES), "r"(smem_base + OFF_MBAR) : "memory");
        asm volatile("mbarrier.arrive.expect_tx.shared.b64 _, [%0], %1;"
                     :: "r"(smem_base + OFF_MBAR + 8), "r"((uint32_t)LOAD_BYTES) : "memory");
        asm volatile("cp.async.bulk.shared::cta.global.mbarrier::complete_tx::bytes "
                     "[%0], [%1], %2, [%3];"
                     :: "r"(smem_base + OFF_IN1), "l"(s1),
                        "r"((uint32_t)LOAD_BYTES), "r"(smem_base + OFF_MBAR + 8) : "memory");
    }

    // ---- projection table (depends only on b; shared by both units) ----
    if (t < NATOMS) {
        const float r = reward[b];
        const float d = discount[b];
        const float z = support[t];
        float Tz = fminf(fmaxf(r + d * z, V_MIN_C), V_MAX_C);
        float bc = (Tz - V_MIN_C) / DZ_C;
        int lo = (int)floorf(bc);
        int up = (int)ceilf(bc);
        if (up > 0 && lo == up) lo -= 1;              // reference fixup 1
        if (lo < NATOMS - 1 && lo == up) up += 1;     // reference fixup 2 => up==lo+1
        stbl[t] = make_float4((float)up - bc, bc - (float)lo,
                              __int_as_float(lo), 0.0f);
    }

    // ---- encode + decode: only when U0 is the first sixth of its batch ----
    if ((c % 3 == 0) && t >= 96 && t < 96 + ADIM) {
        const int dim = t - 96;
        const float a = act[b * ADIM + dim];
        float low = low0[dim], high = high0[dim];
        float idx[LEVELS];
        #pragma unroll
        for (int lvl = 0; lvl < LEVELS; lvl++) {
            float sr = (high - low) / (float)BINS;
            float id = floorf((a - low) / sr);
            id = fminf(fmaxf(id, 0.0f), (float)(BINS - 1));
            float na = fminf(fmaxf(low + sr * id, -1.0f), 1.0f);
            low  = fmaxf(-1.0f, na);
            high = fminf(1.0f, na + sr);
            idx[lvl] = id;
        }
        low = low0[dim]; high = high0[dim];
        #pragma unroll
        for (int lvl = 0; lvl < LEVELS; lvl++) {
            float sr = (high - low) / (float)BINS;
            float cont = low + sr * idx[lvl];
            low  = fmaxf(-1.0f, cont);
            high = fminf(1.0f, cont + sr);
        }
        out[(size_t)NB * SLAB + (size_t)b * ADIM + dim] = 0.5f * (high + low);
    }

    __syncthreads();   // mbar init + table visible to all

    // ---- warp 0 handles unit0; warp 2 handles unit1; warps 1,3 exit ----
    const bool half0 = (t < 32);
    const bool half1 = (t >= 64 && t < 96);
    if (!(half0 || half1)) return;

    const int  lane    = half0 ? t : (t - 64);
    const int  U       = half0 ? U0 : U1;
    const int  m       = half0 ? m0 : m1;
    const int  in_off  = half0 ? OFF_IN0  : OFF_IN1;
    const int  out_off = half0 ? OFF_OUT0 : OFF_OUT1;
    const uint32_t mbar = smem_base + OFF_MBAR + (half0 ? 0u : 8u);

    // ---- wait for this half's slab ----
    asm volatile(
        "{\n\t"
        ".reg .pred P;\n\t"
        "WAIT_%=:\n\t"
        "mbarrier.try_wait.parity.acquire.cta.shared::cta.b64 P, [%0], 0, 0x989680;\n\t"
        "@!P bra WAIT_%=;\n\t"
        "}"
        :: "r"(mbar) : "memory");

    float* sp = reinterpret_cast<float*>(dyn + in_off  + m);
    float* so = reinterpret_cast<float*>(dyn + out_off + m);

    // ---- walk: one thread per row, single pass j=0..50, gap zero-fill ----
    if (lane < TROWS) {
        const float* pr = sp + lane * NATOMS;  // stride 51 (odd) -> conflict-free
        float* po = so + lane * NATOMS;
        int kcur = __float_as_int(stbl[0].z);
        for (int k = 0; k < kcur; k++) po[k] = 0.0f;
        float accA = 0.0f, accB = 0.0f, carryB = 0.0f;
        #pragma unroll 1
        for (int j = 0; j < NATOMS; j++) {
            const float4 tb = stbl[j];         // LDS.128 broadcast
            const int kj = __float_as_int(tb.z);
            if (kj != kcur) {                  // uniform branch
                po[kcur] = accA + carryB;
                if (kj == kcur + 1) {
                    carryB = accB;
                } else {
                    po[kcur + 1] = accB;
                    for (int k = kcur + 2; k < kj; k++) po[k] = 0.0f;
                    carryB = 0.0f;
                }
                accA = 0.0f; accB = 0.0f; kcur = kj;
            }
            const float p = pr[j];
            accA = fmaf(p, tb.x, accA);
            accB = fmaf(p, tb.y, accB);
        }
        po[kcur] = accA + carryB;
        po[kcur + 1] = accB;                   // kcur <= 49 -> safe
        for (int k = kcur + 2; k < NATOMS; k++) po[k] = 0.0f;
    }
    __syncwarp();

    // ---- store: head/tail scalar floats + 16B-aligned interior via bulk ----
    const int h       = ((16 - m) & 15) >> 2;           // head floats (0..3)
    const int rem     = TSLAB_BYTES - h * 4;
    const int interior = rem & ~15;
    const int tailf   = (rem & 15) >> 2;                // tail floats (0..3)
    if (lane < 4) {
        float* dst = out + (size_t)U * TSLAB;
        if (lane < h)     dst[lane] = so[lane];
        if (lane < tailf) dst[TSLAB - 1 - lane] = so[TSLAB - 1 - lane];
    }
    if (lane == 0) {
        asm volatile("fence.proxy.async.shared::cta;" ::: "memory");
        const uint32_t src_s = smem_base + (uint32_t)(out_off + m + h * 4); // 16B aligned
        char* dst_al = reinterpret_cast<char*>(out) + (size_t)U * TSLAB_BYTES + h * 4;
        asm volatile("cp.async.bulk.global.shared::cta.bulk_group [%0], [%1], %2;"
                     :: "l"(dst_al), "r"(src_s), "r"((uint32_t)interior) : "memory");
        asm volatile("cp.async.bulk.commit_group;" ::: "memory");
        asm volatile("cp.async.bulk.wait_group 0;" ::: "memory");
    }
}

extern "C" void kernel_launch(void* const* d_in, const int* in_sizes, int n_in,
                              void* d_out, int out_size)
{
    const float* q        = (const float*)d_in[0];
    const float* reward   = (const float*)d_in[1];
    const float* discount = (const float*)d_in[2];
    const float* act      = (const float*)d_in[3];
    const float* support  = (const float*)d_in[4];
    const float* low0     = (const float*)d_in[5];
    const float* high0    = (const float*)d_in[6];
    float* out = (float*)d_out;

    cudaFuncSetAttribute(c2f_kernel, cudaFuncAttributeMaxDynamicSharedMemorySize,
                         DYN_BYTES);
    c2f_kernel<<<GRID, THREADS, DYN_BYTES>>>(q, reward, discount, act, support,
                                             low0, high0, out);
}